// round 1
// baseline (speedup 1.0000x reference)
#include <cuda_runtime.h>
#include <math.h>

#define N_TOK 2304
#define DIM   384
#define KD    32
#define NHEAD 8
#define DV    128
#define NHKD  256
#define DH    1024
#define QSCALE 0.17677669529663687f   // 32^-0.5

// ---------------- scratch (no allocations allowed) ----------------
__device__ float g_q[N_TOK * NHKD];
__device__ float g_k[N_TOK * NHKD];
__device__ float g_v[N_TOK * DH];
__device__ float g_o[N_TOK * DH];

// ======================================================================
// Generic GEMM: O[m][n] = sum_k X[m][k] * W[n][k] + bias[n]
// BM=BN=64, BK=16, 256 threads, 4x4 register tile per thread.
// All problem dims here are multiples of 64/16, so no bounds checks.
// ======================================================================
__global__ void gemm_xwt(const float* __restrict__ X,
                         const float* __restrict__ W,
                         const float* __restrict__ bias,
                         float* __restrict__ O,
                         int M, int Nn, int K) {
    __shared__ float Xs[16][68];   // [kk][m], pad 68 keeps float4 alignment
    __shared__ float Ws[16][68];   // [kk][n]

    const int t  = threadIdx.x;
    const int ty = t >> 4;         // 0..15 -> 4 rows each
    const int tx = t & 15;         // 0..15 -> 4 cols each
    const int m0 = blockIdx.x * 64;
    const int n0 = blockIdx.y * 64;

    float acc[4][4] = {};

    for (int k0 = 0; k0 < K; k0 += 16) {
        #pragma unroll
        for (int l = 0; l < 4; l++) {
            int lin = t + l * 256;
            int r = lin >> 4;      // 0..63
            int c = lin & 15;      // 0..15
            Xs[c][r] = X[(m0 + r) * K + k0 + c];
            Ws[c][r] = W[(n0 + r) * K + k0 + c];
        }
        __syncthreads();

        #pragma unroll
        for (int kk = 0; kk < 16; kk++) {
            float4 av = *(const float4*)&Xs[kk][ty * 4];
            float4 bv = *(const float4*)&Ws[kk][tx * 4];
            float a[4] = {av.x, av.y, av.z, av.w};
            float b[4] = {bv.x, bv.y, bv.z, bv.w};
            #pragma unroll
            for (int i = 0; i < 4; i++)
                #pragma unroll
                for (int j = 0; j < 4; j++)
                    acc[i][j] += a[i] * b[j];
        }
        __syncthreads();
    }

    #pragma unroll
    for (int i = 0; i < 4; i++) {
        int m = m0 + ty * 4 + i;
        #pragma unroll
        for (int j = 0; j < 4; j++) {
            int n = n0 + tx * 4 + j;
            O[m * Nn + n] = acc[i][j] + bias[n];
        }
    }
}

// ======================================================================
// Fused flash-style attention per (q-tile of 64, head).
// Q: [N, 256] (head slice h*32), K: [N, 256], V: [N, 1024] (slice h*128)
// out g_o: [N, 1024].
// 256 threads. Dynamic smem layout (floats):
//   Qs[64][33] | Ks[64][33] | Vs[64][132] | Ps[64][65] | bias[2304] | m/l/a[64]x3
// ======================================================================
#define SM_QS   0
#define SM_KS   (64 * 33)
#define SM_VS   (SM_KS + 64 * 33)
#define SM_PS   (SM_VS + 64 * 132)
#define SM_BIAS (SM_PS + 64 * 65)
#define SM_M    (SM_BIAS + N_TOK)
#define SM_L    (SM_M + 64)
#define SM_A    (SM_L + 64)
#define SM_FLOATS (SM_A + 64)

__global__ void attn_kernel(const float* __restrict__ Q,
                            const float* __restrict__ K,
                            const float* __restrict__ V,
                            const float* __restrict__ biases,     // [8, 2304]
                            const int*   __restrict__ bias_idx,   // [2304, 2304]
                            float* __restrict__ O) {
    extern __shared__ float sm[];
    float* Qs = sm + SM_QS;
    float* Ks = sm + SM_KS;
    float* Vs = sm + SM_VS;
    float* Ps = sm + SM_PS;
    float* bias_sm = sm + SM_BIAS;
    float* mrow = sm + SM_M;
    float* lrow = sm + SM_L;
    float* arow = sm + SM_A;

    const int t  = threadIdx.x;
    const int qb = blockIdx.x * 64;
    const int h  = blockIdx.y;

    // load Q tile (64 x 32)
    #pragma unroll
    for (int l = 0; l < 8; l++) {
        int lin = t + l * 256;
        int r = lin >> 5, c = lin & 31;
        Qs[r * 33 + c] = Q[(qb + r) * NHKD + h * KD + c];
    }
    // per-head bias table
    for (int i = t; i < N_TOK; i += 256)
        bias_sm[i] = biases[h * N_TOK + i];
    if (t < 64) { mrow[t] = -1e30f; lrow[t] = 0.0f; }

    const int ty = t >> 4;        // 4 q-rows: ty*4..+3
    const int tx = t & 15;        // 8 v-cols: tx*8..+7
    float acc[4][8] = {};

    for (int kt = 0; kt < N_TOK / 64; kt++) {
        const int kb = kt * 64;
        __syncthreads();   // previous accumulate done before overwrite

        // load K tile (64x32) and V tile (64x128, float4)
        #pragma unroll
        for (int l = 0; l < 8; l++) {
            int lin = t + l * 256;
            int r = lin >> 5, c = lin & 31;
            Ks[r * 33 + c] = K[(kb + r) * NHKD + h * KD + c];
        }
        #pragma unroll
        for (int l = 0; l < 8; l++) {
            int lin = t + l * 256;
            int r = lin >> 5, c4 = lin & 31;          // c4: float4 index 0..31
            float4 v = *(const float4*)&V[(kb + r) * DH + h * DV + c4 * 4];
            *(float4*)&Vs[r * 132 + c4 * 4] = v;
        }
        __syncthreads();

        // S = Q K^T * scale + bias  -> Ps  (thread: rows ty*4..+3, cols tx*4..+3)
        {
            const int r0 = ty * 4, c0 = tx * 4;
            float s[4][4] = {};
            #pragma unroll
            for (int kk = 0; kk < KD; kk++) {
                float a[4], b[4];
                #pragma unroll
                for (int i = 0; i < 4; i++) a[i] = Qs[(r0 + i) * 33 + kk];
                #pragma unroll
                for (int j = 0; j < 4; j++) b[j] = Ks[(c0 + j) * 33 + kk];
                #pragma unroll
                for (int i = 0; i < 4; i++)
                    #pragma unroll
                    for (int j = 0; j < 4; j++)
                        s[i][j] += a[i] * b[j];
            }
            #pragma unroll
            for (int i = 0; i < 4; i++) {
                int qg = qb + r0 + i;
                const int* idx_row = bias_idx + (long)qg * N_TOK + kb + c0;
                #pragma unroll
                for (int j = 0; j < 4; j++) {
                    float val = s[i][j] * QSCALE + bias_sm[idx_row[j]];
                    Ps[(r0 + i) * 65 + c0 + j] = val;
                }
            }
        }
        __syncthreads();

        // online softmax per row (threads 0..63)
        if (t < 64) {
            float mold = mrow[t];
            float mnew = mold;
            #pragma unroll 8
            for (int c = 0; c < 64; c++)
                mnew = fmaxf(mnew, Ps[t * 65 + c]);
            float al = __expf(mold - mnew);
            float ssum = 0.0f;
            #pragma unroll 8
            for (int c = 0; c < 64; c++) {
                float p = __expf(Ps[t * 65 + c] - mnew);
                Ps[t * 65 + c] = p;
                ssum += p;
            }
            mrow[t] = mnew;
            lrow[t] = lrow[t] * al + ssum;
            arow[t] = al;
        }
        __syncthreads();

        // accumulate O += P * V   (thread: rows ty*4..+3, cols tx*8..+7)
        {
            const int r0 = ty * 4;
            float al[4];
            #pragma unroll
            for (int i = 0; i < 4; i++) al[i] = arow[r0 + i];
            #pragma unroll
            for (int i = 0; i < 4; i++)
                #pragma unroll
                for (int j = 0; j < 8; j++)
                    acc[i][j] *= al[i];

            #pragma unroll 4
            for (int key = 0; key < 64; key++) {
                float4 v0 = *(const float4*)&Vs[key * 132 + tx * 8];
                float4 v1 = *(const float4*)&Vs[key * 132 + tx * 8 + 4];
                float p[4];
                #pragma unroll
                for (int i = 0; i < 4; i++) p[i] = Ps[(r0 + i) * 65 + key];
                #pragma unroll
                for (int i = 0; i < 4; i++) {
                    acc[i][0] += p[i] * v0.x;
                    acc[i][1] += p[i] * v0.y;
                    acc[i][2] += p[i] * v0.z;
                    acc[i][3] += p[i] * v0.w;
                    acc[i][4] += p[i] * v1.x;
                    acc[i][5] += p[i] * v1.y;
                    acc[i][6] += p[i] * v1.z;
                    acc[i][7] += p[i] * v1.w;
                }
            }
        }
    }

    // epilogue: normalize and write
    const int r0 = ty * 4;
    #pragma unroll
    for (int i = 0; i < 4; i++) {
        float inv = 1.0f / lrow[r0 + i];
        float4 o0 = make_float4(acc[i][0]*inv, acc[i][1]*inv, acc[i][2]*inv, acc[i][3]*inv);
        float4 o1 = make_float4(acc[i][4]*inv, acc[i][5]*inv, acc[i][6]*inv, acc[i][7]*inv);
        float* dst = O + (long)(qb + r0 + i) * DH + h * DV + tx * 8;
        *(float4*)dst = o0;
        *(float4*)(dst + 4) = o1;
    }
}

// ======================================================================
extern "C" void kernel_launch(void* const* d_in, const int* in_sizes, int n_in,
                              void* d_out, int out_size) {
    const float* x       = (const float*)d_in[0];
    const float* q_w     = (const float*)d_in[1];
    const float* q_b     = (const float*)d_in[2];
    const float* k_w     = (const float*)d_in[3];
    const float* k_b     = (const float*)d_in[4];
    const float* v_w     = (const float*)d_in[5];
    const float* v_b     = (const float*)d_in[6];
    const float* proj_w  = (const float*)d_in[7];
    const float* proj_b  = (const float*)d_in[8];
    const float* abias   = (const float*)d_in[9];
    const int*   bidx    = (const int*)d_in[10];
    float* out           = (float*)d_out;

    float *pq, *pk, *pv, *po;
    cudaGetSymbolAddress((void**)&pq, g_q);
    cudaGetSymbolAddress((void**)&pk, g_k);
    cudaGetSymbolAddress((void**)&pv, g_v);
    cudaGetSymbolAddress((void**)&po, g_o);

    // QKV projections
    gemm_xwt<<<dim3(N_TOK / 64, NHKD / 64), 256>>>(x, q_w, q_b, pq, N_TOK, NHKD, DIM);
    gemm_xwt<<<dim3(N_TOK / 64, NHKD / 64), 256>>>(x, k_w, k_b, pk, N_TOK, NHKD, DIM);
    gemm_xwt<<<dim3(N_TOK / 64, DH   / 64), 256>>>(x, v_w, v_b, pv, N_TOK, DH,   DIM);

    // attention
    const int smem_bytes = SM_FLOATS * (int)sizeof(float);
    cudaFuncSetAttribute(attn_kernel, cudaFuncAttributeMaxDynamicSharedMemorySize, smem_bytes);
    attn_kernel<<<dim3(N_TOK / 64, NHEAD), 256, smem_bytes>>>(pq, pk, pv, abias, bidx, po);

    // output projection -> d_out
    gemm_xwt<<<dim3(N_TOK / 64, DIM / 64), 256>>>(po, proj_w, proj_b, out, N_TOK, DIM, DH);
}

// round 2
// speedup vs baseline: 1.4241x; 1.4241x over previous
#include <cuda_runtime.h>
#include <math.h>
#include <stdint.h>

#define N_TOK 2304
#define DIM   384
#define KD    32
#define NHEAD 8
#define DV    128
#define NHKD  256
#define DH    1024
#define RES   48
#define QSCALE 0.17677669529663687f   // 32^-0.5

// ---------------- scratch (no allocations allowed) ----------------
__device__ float g_q[N_TOK * NHKD];
__device__ float g_k[N_TOK * NHKD];
__device__ float g_v[N_TOK * DH];
__device__ float g_o[N_TOK * DH];

// ======================================================================
// Generic GEMM: O[m][n] = sum_k X[m][k] * W[n][k] + bias[n]   (fp32 SIMT)
// ======================================================================
__global__ void gemm_xwt(const float* __restrict__ X,
                         const float* __restrict__ W,
                         const float* __restrict__ bias,
                         float* __restrict__ O,
                         int M, int Nn, int K) {
    __shared__ float Xs[16][68];
    __shared__ float Ws[16][68];

    const int t  = threadIdx.x;
    const int ty = t >> 4;
    const int tx = t & 15;
    const int m0 = blockIdx.x * 64;
    const int n0 = blockIdx.y * 64;

    float acc[4][4] = {};

    for (int k0 = 0; k0 < K; k0 += 16) {
        #pragma unroll
        for (int l = 0; l < 4; l++) {
            int lin = t + l * 256;
            int r = lin >> 4;
            int c = lin & 15;
            Xs[c][r] = X[(m0 + r) * K + k0 + c];
            Ws[c][r] = W[(n0 + r) * K + k0 + c];
        }
        __syncthreads();

        #pragma unroll
        for (int kk = 0; kk < 16; kk++) {
            float4 av = *(const float4*)&Xs[kk][ty * 4];
            float4 bv = *(const float4*)&Ws[kk][tx * 4];
            float a[4] = {av.x, av.y, av.z, av.w};
            float b[4] = {bv.x, bv.y, bv.z, bv.w};
            #pragma unroll
            for (int i = 0; i < 4; i++)
                #pragma unroll
                for (int j = 0; j < 4; j++)
                    acc[i][j] += a[i] * b[j];
        }
        __syncthreads();
    }

    #pragma unroll
    for (int i = 0; i < 4; i++) {
        int m = m0 + ty * 4 + i;
        #pragma unroll
        for (int j = 0; j < 4; j++) {
            int n = n0 + tx * 4 + j;
            O[m * Nn + n] = acc[i][j] + bias[n];
        }
    }
}

// ======================================================================
// tf32 mma helpers
// ======================================================================
__device__ __forceinline__ uint32_t f2tf32(float x) {
    uint32_t r;
    asm("cvt.rna.tf32.f32 %0, %1;" : "=r"(r) : "f"(x));
    return r;
}

__device__ __forceinline__ void mma_tf32(float& d0, float& d1, float& d2, float& d3,
                                         uint32_t a0, uint32_t a1, uint32_t a2, uint32_t a3,
                                         uint32_t b0, uint32_t b1) {
    asm volatile(
        "mma.sync.aligned.m16n8k8.row.col.f32.tf32.tf32.f32 "
        "{%0,%1,%2,%3}, {%4,%5,%6,%7}, {%8,%9}, {%0,%1,%2,%3};\n"
        : "+f"(d0), "+f"(d1), "+f"(d2), "+f"(d3)
        : "r"(a0), "r"(a1), "r"(a2), "r"(a3), "r"(b0), "r"(b1));
}

// ======================================================================
// Flash attention via mma.sync tf32.
// Grid: (18, 8).  256 threads (8 warps).  BM=128 q-rows, key tiles of 64.
// Warp w owns q-rows 16w..16w+15.
// QK^T in 3xTF32 (hi/lo split), P*V in 1xTF32.
// ======================================================================
#define BM 128
#define BN 64
#define KSTR 36     // K smem stride: banks gid*4+tig all distinct
#define VSTR 136    // V smem stride: banks tig*8+gid all distinct
#define PSTR 68     // P smem stride: frag reads conflict-free

// smem float counts
#define SM_KHI  0
#define SM_KLO  (SM_KHI + 64 * KSTR)
#define SM_VS   (SM_KLO + 64 * KSTR)
#define SM_PS   (SM_VS + 64 * VSTR)
#define SM_BIA  (SM_PS + BM * PSTR)
#define SM_TOT  (SM_BIA + N_TOK)
// Qs (128x33 = 4224 floats) aliases Ps (8704 floats): Qs only read before
// the first Ps write, separated by __syncthreads.

__global__ __launch_bounds__(256, 1)
void attn_mma(const float* __restrict__ Q,
              const float* __restrict__ K,
              const float* __restrict__ V,
              const float* __restrict__ biases,   // [8, 2304]
              float* __restrict__ O) {
    extern __shared__ float sm[];
    float* Khi = sm + SM_KHI;
    float* Klo = sm + SM_KLO;
    float* Vs  = sm + SM_VS;
    float* Ps  = sm + SM_PS;
    float* bias_sm = sm + SM_BIA;
    float* Qs  = Ps;                 // alias

    const int t    = threadIdx.x;
    const int w    = t >> 5;
    const int lane = t & 31;
    const int gid  = lane >> 2;      // 0..7
    const int tig  = lane & 3;       // 0..3
    const int qb   = blockIdx.x * BM;
    const int h    = blockIdx.y;

    const int row0 = qb + 16 * w + gid;      // global q row for c0/c1
    const int row1 = row0 + 8;               // for c2/c3
    const int qy0 = row0 / RES, qx0 = row0 % RES;
    const int qy1 = row1 / RES, qx1 = row1 % RES;

    // per-head bias table
    for (int i = t; i < N_TOK; i += 256)
        bias_sm[i] = biases[h * N_TOK + i];

    // stage Q tile (128 x 32) into Qs
    #pragma unroll
    for (int l = 0; l < 16; l++) {
        int lin = t + l * 256;
        int r = lin >> 5, c = lin & 31;
        Qs[r * 33 + c] = Q[(qb + r) * NHKD + h * KD + c];
    }
    __syncthreads();

    // loop-invariant Q fragments (hi/lo tf32 split), 4 k-steps
    uint32_t qhi[4][4], qlo[4][4];
    #pragma unroll
    for (int ks = 0; ks < 4; ks++) {
        int r0l = 16 * w + gid;
        float x0 = Qs[r0l * 33 + ks * 8 + tig];          // a0: row gid, col tig
        float x1 = Qs[(r0l + 8) * 33 + ks * 8 + tig];    // a1: row gid+8
        float x2 = Qs[r0l * 33 + ks * 8 + tig + 4];      // a2: col tig+4
        float x3 = Qs[(r0l + 8) * 33 + ks * 8 + tig + 4];// a3
        uint32_t h0 = f2tf32(x0), h1 = f2tf32(x1), h2 = f2tf32(x2), h3 = f2tf32(x3);
        qhi[ks][0] = h0; qhi[ks][1] = h1; qhi[ks][2] = h2; qhi[ks][3] = h3;
        qlo[ks][0] = f2tf32(x0 - __uint_as_float(h0));
        qlo[ks][1] = f2tf32(x1 - __uint_as_float(h1));
        qlo[ks][2] = f2tf32(x2 - __uint_as_float(h2));
        qlo[ks][3] = f2tf32(x3 - __uint_as_float(h3));
    }

    float m_r0 = -1e30f, m_r1 = -1e30f;
    float l_r0 = 0.0f,   l_r1 = 0.0f;
    float o[16][4];
    #pragma unroll
    for (int nt = 0; nt < 16; nt++)
        #pragma unroll
        for (int i = 0; i < 4; i++) o[nt][i] = 0.0f;

    for (int kt = 0; kt < N_TOK / BN; kt++) {
        const int kb = kt * BN;

        // fill K hi/lo (64x32)
        #pragma unroll
        for (int l = 0; l < 8; l++) {
            int lin = t + l * 256;
            int r = lin >> 5, c = lin & 31;
            float x = K[(kb + r) * NHKD + h * KD + c];
            uint32_t hb = f2tf32(x);
            Khi[r * KSTR + c] = __uint_as_float(hb);
            Klo[r * KSTR + c] = __uint_as_float(f2tf32(x - __uint_as_float(hb)));
        }
        // fill V (64x128), tf32-rounded
        #pragma unroll
        for (int l = 0; l < 8; l++) {
            int lin = t + l * 256;
            int r = lin >> 5, c4 = lin & 31;
            float4 v = *(const float4*)&V[(kb + r) * DH + h * DV + c4 * 4];
            float4 tv;
            tv.x = __uint_as_float(f2tf32(v.x));
            tv.y = __uint_as_float(f2tf32(v.y));
            tv.z = __uint_as_float(f2tf32(v.z));
            tv.w = __uint_as_float(f2tf32(v.w));
            *(float4*)&Vs[r * VSTR + c4 * 4] = tv;
        }
        __syncthreads();

        // ---- S = Q K^T (3x tf32) ----
        float sfr[8][4];
        #pragma unroll
        for (int nt = 0; nt < 8; nt++)
            #pragma unroll
            for (int i = 0; i < 4; i++) sfr[nt][i] = 0.0f;

        #pragma unroll
        for (int ks = 0; ks < 4; ks++) {
            #pragma unroll
            for (int nt = 0; nt < 8; nt++) {
                int nrow = nt * 8 + gid;
                uint32_t bh0 = __float_as_uint(Khi[nrow * KSTR + ks * 8 + tig]);
                uint32_t bh1 = __float_as_uint(Khi[nrow * KSTR + ks * 8 + tig + 4]);
                uint32_t bl0 = __float_as_uint(Klo[nrow * KSTR + ks * 8 + tig]);
                uint32_t bl1 = __float_as_uint(Klo[nrow * KSTR + ks * 8 + tig + 4]);
                mma_tf32(sfr[nt][0], sfr[nt][1], sfr[nt][2], sfr[nt][3],
                         qhi[ks][0], qhi[ks][1], qhi[ks][2], qhi[ks][3], bh0, bh1);
                mma_tf32(sfr[nt][0], sfr[nt][1], sfr[nt][2], sfr[nt][3],
                         qlo[ks][0], qlo[ks][1], qlo[ks][2], qlo[ks][3], bh0, bh1);
                mma_tf32(sfr[nt][0], sfr[nt][1], sfr[nt][2], sfr[nt][3],
                         qhi[ks][0], qhi[ks][1], qhi[ks][2], qhi[ks][3], bl0, bl1);
            }
        }

        // ---- scale + bias, row max ----
        float mx0 = -1e30f, mx1 = -1e30f;
        #pragma unroll
        for (int nt = 0; nt < 8; nt++) {
            int ck0 = kb + nt * 8 + 2 * tig;
            int ck1 = ck0 + 1;
            int ky0 = ck0 / RES, kx0 = ck0 % RES;
            int ky1 = ck1 / RES, kx1 = ck1 % RES;
            float b00 = bias_sm[abs(qy0 - ky0) * RES + abs(qx0 - kx0)];
            float b01 = bias_sm[abs(qy0 - ky1) * RES + abs(qx0 - kx1)];
            float b10 = bias_sm[abs(qy1 - ky0) * RES + abs(qx1 - kx0)];
            float b11 = bias_sm[abs(qy1 - ky1) * RES + abs(qx1 - kx1)];
            sfr[nt][0] = sfr[nt][0] * QSCALE + b00;
            sfr[nt][1] = sfr[nt][1] * QSCALE + b01;
            sfr[nt][2] = sfr[nt][2] * QSCALE + b10;
            sfr[nt][3] = sfr[nt][3] * QSCALE + b11;
            mx0 = fmaxf(mx0, fmaxf(sfr[nt][0], sfr[nt][1]));
            mx1 = fmaxf(mx1, fmaxf(sfr[nt][2], sfr[nt][3]));
        }
        mx0 = fmaxf(mx0, __shfl_xor_sync(0xffffffffu, mx0, 1));
        mx0 = fmaxf(mx0, __shfl_xor_sync(0xffffffffu, mx0, 2));
        mx1 = fmaxf(mx1, __shfl_xor_sync(0xffffffffu, mx1, 1));
        mx1 = fmaxf(mx1, __shfl_xor_sync(0xffffffffu, mx1, 2));

        float mn0 = fmaxf(m_r0, mx0);
        float mn1 = fmaxf(m_r1, mx1);
        float al0 = __expf(m_r0 - mn0);
        float al1 = __expf(m_r1 - mn1);
        m_r0 = mn0; m_r1 = mn1;

        // ---- P = exp(S - m), write tf32 P to smem, row sums ----
        float sum0 = 0.0f, sum1 = 0.0f;
        const int prow0 = (16 * w + gid) * PSTR;
        const int prow1 = (16 * w + gid + 8) * PSTR;
        #pragma unroll
        for (int nt = 0; nt < 8; nt++) {
            float p0 = __expf(sfr[nt][0] - mn0);
            float p1 = __expf(sfr[nt][1] - mn0);
            float p2 = __expf(sfr[nt][2] - mn1);
            float p3 = __expf(sfr[nt][3] - mn1);
            sum0 += p0 + p1;
            sum1 += p2 + p3;
            float2 w0, w1;
            w0.x = __uint_as_float(f2tf32(p0));
            w0.y = __uint_as_float(f2tf32(p1));
            w1.x = __uint_as_float(f2tf32(p2));
            w1.y = __uint_as_float(f2tf32(p3));
            *(float2*)&Ps[prow0 + nt * 8 + 2 * tig] = w0;
            *(float2*)&Ps[prow1 + nt * 8 + 2 * tig] = w1;
        }
        sum0 += __shfl_xor_sync(0xffffffffu, sum0, 1);
        sum0 += __shfl_xor_sync(0xffffffffu, sum0, 2);
        sum1 += __shfl_xor_sync(0xffffffffu, sum1, 1);
        sum1 += __shfl_xor_sync(0xffffffffu, sum1, 2);
        l_r0 = l_r0 * al0 + sum0;
        l_r1 = l_r1 * al1 + sum1;

        // rescale O accumulators
        #pragma unroll
        for (int nt = 0; nt < 16; nt++) {
            o[nt][0] *= al0; o[nt][1] *= al0;
            o[nt][2] *= al1; o[nt][3] *= al1;
        }
        __syncthreads();   // Ps visible to all warps

        // ---- O += P * V (1x tf32) ----
        #pragma unroll
        for (int ks = 0; ks < 8; ks++) {
            uint32_t pa0 = __float_as_uint(Ps[prow0 + ks * 8 + tig]);
            uint32_t pa1 = __float_as_uint(Ps[prow1 + ks * 8 + tig]);
            uint32_t pa2 = __float_as_uint(Ps[prow0 + ks * 8 + tig + 4]);
            uint32_t pa3 = __float_as_uint(Ps[prow1 + ks * 8 + tig + 4]);
            #pragma unroll
            for (int nt = 0; nt < 16; nt++) {
                uint32_t vb0 = __float_as_uint(Vs[(ks * 8 + tig) * VSTR + nt * 8 + gid]);
                uint32_t vb1 = __float_as_uint(Vs[(ks * 8 + tig + 4) * VSTR + nt * 8 + gid]);
                mma_tf32(o[nt][0], o[nt][1], o[nt][2], o[nt][3],
                         pa0, pa1, pa2, pa3, vb0, vb1);
            }
        }
        __syncthreads();   // done with Khi/Klo/Vs/Ps before next fill
    }

    // ---- epilogue ----
    float inv0 = 1.0f / l_r0;
    float inv1 = 1.0f / l_r1;
    #pragma unroll
    for (int nt = 0; nt < 16; nt++) {
        float2 r0, r1;
        r0.x = o[nt][0] * inv0; r0.y = o[nt][1] * inv0;
        r1.x = o[nt][2] * inv1; r1.y = o[nt][3] * inv1;
        *(float2*)&O[(long)row0 * DH + h * DV + nt * 8 + 2 * tig] = r0;
        *(float2*)&O[(long)row1 * DH + h * DV + nt * 8 + 2 * tig] = r1;
    }
}

// ======================================================================
extern "C" void kernel_launch(void* const* d_in, const int* in_sizes, int n_in,
                              void* d_out, int out_size) {
    const float* x       = (const float*)d_in[0];
    const float* q_w     = (const float*)d_in[1];
    const float* q_b     = (const float*)d_in[2];
    const float* k_w     = (const float*)d_in[3];
    const float* k_b     = (const float*)d_in[4];
    const float* v_w     = (const float*)d_in[5];
    const float* v_b     = (const float*)d_in[6];
    const float* proj_w  = (const float*)d_in[7];
    const float* proj_b  = (const float*)d_in[8];
    const float* abias   = (const float*)d_in[9];
    float* out           = (float*)d_out;

    float *pq, *pk, *pv, *po;
    cudaGetSymbolAddress((void**)&pq, g_q);
    cudaGetSymbolAddress((void**)&pk, g_k);
    cudaGetSymbolAddress((void**)&pv, g_v);
    cudaGetSymbolAddress((void**)&po, g_o);

    // QKV projections
    gemm_xwt<<<dim3(N_TOK / 64, NHKD / 64), 256>>>(x, q_w, q_b, pq, N_TOK, NHKD, DIM);
    gemm_xwt<<<dim3(N_TOK / 64, NHKD / 64), 256>>>(x, k_w, k_b, pk, N_TOK, NHKD, DIM);
    gemm_xwt<<<dim3(N_TOK / 64, DH   / 64), 256>>>(x, v_w, v_b, pv, N_TOK, DH,   DIM);

    // fused attention (tf32 mma flash)
    const int smem_bytes = SM_TOT * (int)sizeof(float);
    cudaFuncSetAttribute(attn_mma, cudaFuncAttributeMaxDynamicSharedMemorySize, smem_bytes);
    attn_mma<<<dim3(N_TOK / BM, NHEAD), 256, smem_bytes>>>(pq, pk, pv, abias, po);

    // output projection -> d_out
    gemm_xwt<<<dim3(N_TOK / 64, DIM / 64), 256>>>(po, proj_w, proj_b, out, N_TOK, DIM, DH);
}

// round 4
// speedup vs baseline: 2.5344x; 1.7796x over previous
#include <cuda_runtime.h>
#include <math.h>
#include <stdint.h>

#define N_TOK 2304
#define DIM   384
#define KD    32
#define NHEAD 8
#define DV    128
#define NHKD  256
#define DH    1024
#define RES   48
#define QSCALE 0.17677669529663687f   // 32^-0.5

// ---------------- scratch (no allocations allowed) ----------------
__device__ float g_qh [NHEAD * N_TOK * KD];   // head-major Q fp32
__device__ float g_khi[NHEAD * N_TOK * KD];   // head-major K hi (tf32 vals)
__device__ float g_klo[NHEAD * N_TOK * KD];   // head-major K lo (tf32 vals)
__device__ float g_vt [NHEAD * N_TOK * DV];   // head-major V (tf32 vals)
__device__ float g_o  [N_TOK * DH];           // attn out [n][1024]

// ======================================================================
// helpers
// ======================================================================
__device__ __forceinline__ uint32_t f2tf32(float x) {
    uint32_t r;
    asm("cvt.rna.tf32.f32 %0, %1;" : "=r"(r) : "f"(x));
    return r;
}

__device__ __forceinline__ void mma_tf32(float& d0, float& d1, float& d2, float& d3,
                                         uint32_t a0, uint32_t a1, uint32_t a2, uint32_t a3,
                                         uint32_t b0, uint32_t b1) {
    asm volatile(
        "mma.sync.aligned.m16n8k8.row.col.f32.tf32.tf32.f32 "
        "{%0,%1,%2,%3}, {%4,%5,%6,%7}, {%8,%9}, {%0,%1,%2,%3};\n"
        : "+f"(d0), "+f"(d1), "+f"(d2), "+f"(d3)
        : "r"(a0), "r"(a1), "r"(a2), "r"(a3), "r"(b0), "r"(b1));
}

__device__ __forceinline__ void cp_async16(uint32_t dst, const float* src) {
    asm volatile("cp.async.cg.shared.global [%0], [%1], 16;" :: "r"(dst), "l"(src));
}
__device__ __forceinline__ void cp_commit() {
    asm volatile("cp.async.commit_group;");
}

// ======================================================================
// Fused QKV projection GEMM.  O = X @ W^T + b with transformed epilogues.
// grid (36, 24): y<4 -> Q block, y<8 -> K block, else V block.
// ======================================================================
__global__ void qkv_gemm(const float* __restrict__ X,
                         const float* __restrict__ qw, const float* __restrict__ qbias,
                         const float* __restrict__ kw, const float* __restrict__ kbias,
                         const float* __restrict__ vw, const float* __restrict__ vbias) {
    __shared__ float Xs[16][68];
    __shared__ float Ws[16][68];

    const int t  = threadIdx.x;
    const int ty = t >> 4;
    const int tx = t & 15;
    const int m0 = blockIdx.x * 64;

    int seg, nbase;
    const float *W, *B;
    if (blockIdx.y < 4)      { seg = 0; W = qw; B = qbias; nbase = blockIdx.y * 64; }
    else if (blockIdx.y < 8) { seg = 1; W = kw; B = kbias; nbase = (blockIdx.y - 4) * 64; }
    else                     { seg = 2; W = vw; B = vbias; nbase = (blockIdx.y - 8) * 64; }

    float acc[4][4] = {};

    for (int k0 = 0; k0 < DIM; k0 += 16) {
        #pragma unroll
        for (int l = 0; l < 4; l++) {
            int lin = t + l * 256;
            int r = lin >> 4;
            int c = lin & 15;
            Xs[c][r] = X[(m0 + r) * DIM + k0 + c];
            Ws[c][r] = W[(nbase + r) * DIM + k0 + c];
        }
        __syncthreads();

        #pragma unroll
        for (int kk = 0; kk < 16; kk++) {
            float4 av = *(const float4*)&Xs[kk][ty * 4];
            float4 bv = *(const float4*)&Ws[kk][tx * 4];
            float a[4] = {av.x, av.y, av.z, av.w};
            float b[4] = {bv.x, bv.y, bv.z, bv.w};
            #pragma unroll
            for (int i = 0; i < 4; i++)
                #pragma unroll
                for (int j = 0; j < 4; j++)
                    acc[i][j] += a[i] * b[j];
        }
        __syncthreads();
    }

    #pragma unroll
    for (int i = 0; i < 4; i++) {
        int m = m0 + ty * 4 + i;
        #pragma unroll
        for (int j = 0; j < 4; j++) {
            int n = nbase + tx * 4 + j;
            float val = acc[i][j] + B[n];
            if (seg == 0) {
                int hh = n >> 5, c = n & 31;
                g_qh[(hh * N_TOK + m) * KD + c] = val;
            } else if (seg == 1) {
                int hh = n >> 5, c = n & 31;
                uint32_t hb = f2tf32(val);
                g_khi[(hh * N_TOK + m) * KD + c] = __uint_as_float(hb);
                g_klo[(hh * N_TOK + m) * KD + c] =
                    __uint_as_float(f2tf32(val - __uint_as_float(hb)));
            } else {
                int hh = n >> 7, c = n & 127;
                g_vt[(hh * N_TOK + m) * DV + c] = __uint_as_float(f2tf32(val));
            }
        }
    }
}

// ======================================================================
// Output projection GEMM (fp32 SIMT), O[m][n] = sum X[m][k] W[n][k] + b[n]
// ======================================================================
__global__ void gemm_xwt(const float* __restrict__ X,
                         const float* __restrict__ W,
                         const float* __restrict__ bias,
                         float* __restrict__ O,
                         int M, int Nn, int K) {
    __shared__ float Xs[16][68];
    __shared__ float Ws[16][68];

    const int t  = threadIdx.x;
    const int ty = t >> 4;
    const int tx = t & 15;
    const int m0 = blockIdx.x * 64;
    const int n0 = blockIdx.y * 64;

    float acc[4][4] = {};

    for (int k0 = 0; k0 < K; k0 += 16) {
        #pragma unroll
        for (int l = 0; l < 4; l++) {
            int lin = t + l * 256;
            int r = lin >> 4;
            int c = lin & 15;
            Xs[c][r] = X[(m0 + r) * K + k0 + c];
            Ws[c][r] = W[(n0 + r) * K + k0 + c];
        }
        __syncthreads();

        #pragma unroll
        for (int kk = 0; kk < 16; kk++) {
            float4 av = *(const float4*)&Xs[kk][ty * 4];
            float4 bv = *(const float4*)&Ws[kk][tx * 4];
            float a[4] = {av.x, av.y, av.z, av.w};
            float b[4] = {bv.x, bv.y, bv.z, bv.w};
            #pragma unroll
            for (int i = 0; i < 4; i++)
                #pragma unroll
                for (int j = 0; j < 4; j++)
                    acc[i][j] += a[i] * b[j];
        }
        __syncthreads();
    }

    #pragma unroll
    for (int i = 0; i < 4; i++) {
        int m = m0 + ty * 4 + i;
        #pragma unroll
        for (int j = 0; j < 4; j++) {
            int n = n0 + tx * 4 + j;
            O[m * Nn + n] = acc[i][j] + bias[n];
        }
    }
}

// ======================================================================
// Flash attention, tf32 mma, cp.async double-buffered pipeline.
// Grid (18, 8), 256 threads (8 warps), BM=128 q rows, key tiles of 64.
// ======================================================================
#define BM 128
#define BN 64
#define NTILE (N_TOK / BN)
#define KSTR 36
#define VSTR 136
#define PSTR 68

// smem float offsets (double-buffered K and V)
#define OF_K(b)  ((b) * 4608)            // Khi at +0, Klo at +2304
#define OF_V(b)  (9216 + (b) * 8704)
#define OF_PS    26624
#define OF_BIA   35328
#define SM_TOT   37632                    // floats = 150528 bytes

__global__ __launch_bounds__(256, 1)
void attn_mma(const float* __restrict__ Qg,
              const float* __restrict__ Khig,
              const float* __restrict__ Klog,
              const float* __restrict__ Vg,
              const float* __restrict__ biases,   // [8, 2304]
              float* __restrict__ O) {
    extern __shared__ float sm[];
    const uint32_t smb = (uint32_t)__cvta_generic_to_shared(sm);
    float* Ps = sm + OF_PS;
    float* bias_sm = sm + OF_BIA;

    const int t    = threadIdx.x;
    const int w    = t >> 5;
    const int lane = t & 31;
    const int gid  = lane >> 2;
    const int tig  = lane & 3;
    const int qb   = blockIdx.x * BM;
    const int h    = blockIdx.y;

    const float* Kh_base = Khig + (h * N_TOK) * KD;
    const float* Kl_base = Klog + (h * N_TOK) * KD;
    const float* V_base  = Vg   + (h * N_TOK) * DV;

    const int row0 = qb + 16 * w + gid;
    const int row1 = row0 + 8;
    const int qy0 = row0 / RES, qx0 = row0 % RES;
    const int qy1 = row1 / RES, qx1 = row1 % RES;

    // per-head bias table
    for (int i = t; i < N_TOK; i += 256)
        bias_sm[i] = biases[h * N_TOK + i];

    // loop-invariant Q fragments, direct from head-major global
    uint32_t qhi[4][4], qlo[4][4];
    {
        const float* Qrow0 = Qg + (h * N_TOK + row0) * KD;
        const float* Qrow1 = Qg + (h * N_TOK + row1) * KD;
        #pragma unroll
        for (int ks = 0; ks < 4; ks++) {
            float x0 = Qrow0[ks * 8 + tig];
            float x1 = Qrow1[ks * 8 + tig];
            float x2 = Qrow0[ks * 8 + tig + 4];
            float x3 = Qrow1[ks * 8 + tig + 4];
            uint32_t h0 = f2tf32(x0), h1 = f2tf32(x1), h2 = f2tf32(x2), h3 = f2tf32(x3);
            qhi[ks][0] = h0; qhi[ks][1] = h1; qhi[ks][2] = h2; qhi[ks][3] = h3;
            qlo[ks][0] = f2tf32(x0 - __uint_as_float(h0));
            qlo[ks][1] = f2tf32(x1 - __uint_as_float(h1));
            qlo[ks][2] = f2tf32(x2 - __uint_as_float(h2));
            qlo[ks][3] = f2tf32(x3 - __uint_as_float(h3));
        }
    }

    // ---- async tile loader ----
    auto issue_tile = [&](int kt, int b) {
        const int kb = kt * BN;
        const float* kh = Kh_base + kb * KD;
        const float* kl = Kl_base + kb * KD;
        const float* vv = V_base + kb * DV;
        #pragma unroll
        for (int i = 0; i < 2; i++) {
            int c = t + i * 256;            // 0..511
            int r = c >> 3, f4 = c & 7;
            cp_async16(smb + (OF_K(b) + r * KSTR + f4 * 4) * 4, kh + r * KD + f4 * 4);
            cp_async16(smb + (OF_K(b) + 2304 + r * KSTR + f4 * 4) * 4, kl + r * KD + f4 * 4);
        }
        #pragma unroll
        for (int i = 0; i < 8; i++) {
            int c = t + i * 256;            // 0..2047
            int r = c >> 5, f4 = c & 31;
            cp_async16(smb + (OF_V(b) + r * VSTR + f4 * 4) * 4, vv + r * DV + f4 * 4);
        }
    };

    float m_r0 = -1e30f, m_r1 = -1e30f;
    float l_r0 = 0.0f,   l_r1 = 0.0f;
    float o[16][4];
    #pragma unroll
    for (int nt = 0; nt < 16; nt++)
        #pragma unroll
        for (int i = 0; i < 4; i++) o[nt][i] = 0.0f;

    issue_tile(0, 0);
    cp_commit();

    for (int kt = 0; kt < NTILE; kt++) {
        const int b  = kt & 1;
        const int kb = kt * BN;
        float* Khi = sm + OF_K(b);
        float* Klo = Khi + 2304;
        float* Vs  = sm + OF_V(b);

        if (kt + 1 < NTILE) {
            issue_tile(kt + 1, b ^ 1);
            cp_commit();
            asm volatile("cp.async.wait_group 1;");
        } else {
            asm volatile("cp.async.wait_group 0;");
        }
        __syncthreads();

        // ---- S = Q K^T (3x tf32) ----
        float sfr[8][4];
        #pragma unroll
        for (int nt = 0; nt < 8; nt++)
            #pragma unroll
            for (int i = 0; i < 4; i++) sfr[nt][i] = 0.0f;

        #pragma unroll
        for (int ks = 0; ks < 4; ks++) {
            #pragma unroll
            for (int nt = 0; nt < 8; nt++) {
                int nrow = nt * 8 + gid;
                uint32_t bh0 = __float_as_uint(Khi[nrow * KSTR + ks * 8 + tig]);
                uint32_t bh1 = __float_as_uint(Khi[nrow * KSTR + ks * 8 + tig + 4]);
                uint32_t bl0 = __float_as_uint(Klo[nrow * KSTR + ks * 8 + tig]);
                uint32_t bl1 = __float_as_uint(Klo[nrow * KSTR + ks * 8 + tig + 4]);
                mma_tf32(sfr[nt][0], sfr[nt][1], sfr[nt][2], sfr[nt][3],
                         qhi[ks][0], qhi[ks][1], qhi[ks][2], qhi[ks][3], bh0, bh1);
                mma_tf32(sfr[nt][0], sfr[nt][1], sfr[nt][2], sfr[nt][3],
                         qlo[ks][0], qlo[ks][1], qlo[ks][2], qlo[ks][3], bh0, bh1);
                mma_tf32(sfr[nt][0], sfr[nt][1], sfr[nt][2], sfr[nt][3],
                         qhi[ks][0], qhi[ks][1], qhi[ks][2], qhi[ks][3], bl0, bl1);
            }
        }

        // ---- scale + bias, row max ----
        float mx0 = -1e30f, mx1 = -1e30f;
        #pragma unroll
        for (int nt = 0; nt < 8; nt++) {
            int ck0 = kb + nt * 8 + 2 * tig;
            int ck1 = ck0 + 1;
            int ky0 = ck0 / RES, kx0 = ck0 % RES;
            int ky1 = ck1 / RES, kx1 = ck1 % RES;
            float b00 = bias_sm[abs(qy0 - ky0) * RES + abs(qx0 - kx0)];
            float b01 = bias_sm[abs(qy0 - ky1) * RES + abs(qx0 - kx1)];
            float b10 = bias_sm[abs(qy1 - ky0) * RES + abs(qx1 - kx0)];
            float b11 = bias_sm[abs(qy1 - ky1) * RES + abs(qx1 - kx1)];
            sfr[nt][0] = sfr[nt][0] * QSCALE + b00;
            sfr[nt][1] = sfr[nt][1] * QSCALE + b01;
            sfr[nt][2] = sfr[nt][2] * QSCALE + b10;
            sfr[nt][3] = sfr[nt][3] * QSCALE + b11;
            mx0 = fmaxf(mx0, fmaxf(sfr[nt][0], sfr[nt][1]));
            mx1 = fmaxf(mx1, fmaxf(sfr[nt][2], sfr[nt][3]));
        }
        mx0 = fmaxf(mx0, __shfl_xor_sync(0xffffffffu, mx0, 1));
        mx0 = fmaxf(mx0, __shfl_xor_sync(0xffffffffu, mx0, 2));
        mx1 = fmaxf(mx1, __shfl_xor_sync(0xffffffffu, mx1, 1));
        mx1 = fmaxf(mx1, __shfl_xor_sync(0xffffffffu, mx1, 2));

        float mn0 = fmaxf(m_r0, mx0);
        float mn1 = fmaxf(m_r1, mx1);
        float al0 = __expf(m_r0 - mn0);
        float al1 = __expf(m_r1 - mn1);
        m_r0 = mn0; m_r1 = mn1;

        // ---- P = exp(S - m), tf32 into smem, row sums ----
        float sum0 = 0.0f, sum1 = 0.0f;
        const int prow0 = (16 * w + gid) * PSTR;
        const int prow1 = (16 * w + gid + 8) * PSTR;
        #pragma unroll
        for (int nt = 0; nt < 8; nt++) {
            float p0 = __expf(sfr[nt][0] - mn0);
            float p1 = __expf(sfr[nt][1] - mn0);
            float p2 = __expf(sfr[nt][2] - mn1);
            float p3 = __expf(sfr[nt][3] - mn1);
            sum0 += p0 + p1;
            sum1 += p2 + p3;
            float2 w0, w1;
            w0.x = __uint_as_float(f2tf32(p0));
            w0.y = __uint_as_float(f2tf32(p1));
            w1.x = __uint_as_float(f2tf32(p2));
            w1.y = __uint_as_float(f2tf32(p3));
            *(float2*)&Ps[prow0 + nt * 8 + 2 * tig] = w0;
            *(float2*)&Ps[prow1 + nt * 8 + 2 * tig] = w1;
        }
        sum0 += __shfl_xor_sync(0xffffffffu, sum0, 1);
        sum0 += __shfl_xor_sync(0xffffffffu, sum0, 2);
        sum1 += __shfl_xor_sync(0xffffffffu, sum1, 1);
        sum1 += __shfl_xor_sync(0xffffffffu, sum1, 2);
        l_r0 = l_r0 * al0 + sum0;
        l_r1 = l_r1 * al1 + sum1;

        // rescale O accumulators
        #pragma unroll
        for (int nt = 0; nt < 16; nt++) {
            o[nt][0] *= al0; o[nt][1] *= al0;
            o[nt][2] *= al1; o[nt][3] *= al1;
        }
        __syncthreads();   // Ps visible to all warps

        // ---- O += P * V (1x tf32) ----
        #pragma unroll
        for (int ks = 0; ks < 8; ks++) {
            uint32_t pa0 = __float_as_uint(Ps[prow0 + ks * 8 + tig]);
            uint32_t pa1 = __float_as_uint(Ps[prow1 + ks * 8 + tig]);
            uint32_t pa2 = __float_as_uint(Ps[prow0 + ks * 8 + tig + 4]);
            uint32_t pa3 = __float_as_uint(Ps[prow1 + ks * 8 + tig + 4]);
            #pragma unroll
            for (int nt = 0; nt < 16; nt++) {
                uint32_t vb0 = __float_as_uint(Vs[(ks * 8 + tig) * VSTR + nt * 8 + gid]);
                uint32_t vb1 = __float_as_uint(Vs[(ks * 8 + tig + 4) * VSTR + nt * 8 + gid]);
                mma_tf32(o[nt][0], o[nt][1], o[nt][2], o[nt][3],
                         pa0, pa1, pa2, pa3, vb0, vb1);
            }
        }
        __syncthreads();   // done with this buffer + Ps before refill
    }

    // ---- epilogue ----
    float inv0 = 1.0f / l_r0;
    float inv1 = 1.0f / l_r1;
    #pragma unroll
    for (int nt = 0; nt < 16; nt++) {
        float2 r0, r1;
        r0.x = o[nt][0] * inv0; r0.y = o[nt][1] * inv0;
        r1.x = o[nt][2] * inv1; r1.y = o[nt][3] * inv1;
        *(float2*)&O[(long)row0 * DH + h * DV + nt * 8 + 2 * tig] = r0;
        *(float2*)&O[(long)row1 * DH + h * DV + nt * 8 + 2 * tig] = r1;
    }
}

// ======================================================================
extern "C" void kernel_launch(void* const* d_in, const int* in_sizes, int n_in,
                              void* d_out, int out_size) {
    const float* x       = (const float*)d_in[0];
    const float* q_w     = (const float*)d_in[1];
    const float* q_b     = (const float*)d_in[2];
    const float* k_w     = (const float*)d_in[3];
    const float* k_b     = (const float*)d_in[4];
    const float* v_w     = (const float*)d_in[5];
    const float* v_b     = (const float*)d_in[6];
    const float* proj_w  = (const float*)d_in[7];
    const float* proj_b  = (const float*)d_in[8];
    const float* abias   = (const float*)d_in[9];
    float* out           = (float*)d_out;

    float *pq, *pkh, *pkl, *pv, *po;
    cudaGetSymbolAddress((void**)&pq,  g_qh);
    cudaGetSymbolAddress((void**)&pkh, g_khi);
    cudaGetSymbolAddress((void**)&pkl, g_klo);
    cudaGetSymbolAddress((void**)&pv,  g_vt);
    cudaGetSymbolAddress((void**)&po,  g_o);

    // fused QKV projection (epilogue pre-splits K hi/lo, rounds V to tf32)
    qkv_gemm<<<dim3(N_TOK / 64, 24), 256>>>(x, q_w, q_b, k_w, k_b, v_w, v_b);

    // fused attention (tf32 mma flash, cp.async pipelined)
    const int smem_bytes = SM_TOT * (int)sizeof(float);
    cudaFuncSetAttribute(attn_mma, cudaFuncAttributeMaxDynamicSharedMemorySize, smem_bytes);
    attn_mma<<<dim3(N_TOK / BM, NHEAD), 256, smem_bytes>>>(pq, pkh, pkl, pv, abias, po);

    // output projection -> d_out
    gemm_xwt<<<dim3(N_TOK / 64, DIM / 64), 256>>>(po, proj_w, proj_b, out, N_TOK, DIM, DH);
}

// round 5
// speedup vs baseline: 2.9869x; 1.1786x over previous
#include <cuda_runtime.h>
#include <math.h>
#include <stdint.h>

#define N_TOK 2304
#define DIM   384
#define KD    32
#define NHEAD 8
#define DV    128
#define NHKD  256
#define DH    1024
#define RES   48
#define QSCALE 0.17677669529663687f   // 32^-0.5

// ---------------- scratch (no allocations allowed) ----------------
__device__ float g_qh [NHEAD * N_TOK * KD];   // head-major Q fp32
__device__ float g_khi[NHEAD * N_TOK * KD];   // head-major K hi (tf32)
__device__ float g_klo[NHEAD * N_TOK * KD];   // head-major K lo (tf32)
__device__ float g_vt [NHEAD * N_TOK * DV];   // head-major V (tf32)
__device__ float g_ohi[N_TOK * DH];           // attn out hi (tf32)
__device__ float g_olo[N_TOK * DH];           // attn out lo (tf32)

__device__ float g_xhi [N_TOK * DIM],  g_xlo [N_TOK * DIM];
__device__ float g_qwhi[NHKD * DIM],   g_qwlo[NHKD * DIM];
__device__ float g_kwhi[NHKD * DIM],   g_kwlo[NHKD * DIM];
__device__ float g_vwhi[DH * DIM],     g_vwlo[DH * DIM];
__device__ float g_pwhi[DIM * DH],     g_pwlo[DIM * DH];

// ======================================================================
// helpers
// ======================================================================
__device__ __forceinline__ uint32_t f2tf32(float x) {
    uint32_t r;
    asm("cvt.rna.tf32.f32 %0, %1;" : "=r"(r) : "f"(x));
    return r;
}

__device__ __forceinline__ void mma_tf32(float& d0, float& d1, float& d2, float& d3,
                                         uint32_t a0, uint32_t a1, uint32_t a2, uint32_t a3,
                                         uint32_t b0, uint32_t b1) {
    asm volatile(
        "mma.sync.aligned.m16n8k8.row.col.f32.tf32.tf32.f32 "
        "{%0,%1,%2,%3}, {%4,%5,%6,%7}, {%8,%9}, {%0,%1,%2,%3};\n"
        : "+f"(d0), "+f"(d1), "+f"(d2), "+f"(d3)
        : "r"(a0), "r"(a1), "r"(a2), "r"(a3), "r"(b0), "r"(b1));
}

__device__ __forceinline__ void cp_async16(uint32_t dst, const float* src) {
    asm volatile("cp.async.cg.shared.global [%0], [%1], 16;" :: "r"(dst), "l"(src));
}
__device__ __forceinline__ void cp_commit() {
    asm volatile("cp.async.commit_group;");
}

// ======================================================================
// split_prep: hi/lo tf32 split of x and the four weight matrices.
// ======================================================================
#define XN  (N_TOK * DIM)     // 884736
#define QWN (NHKD * DIM)      // 98304
#define VWN (DH * DIM)        // 393216
#define PWN (DIM * DH)        // 393216
#define PREP_TOT (XN + 2 * QWN + VWN + PWN)   // 1867776 = 7296*256

__global__ void split_prep(const float* __restrict__ x,  const float* __restrict__ qw,
                           const float* __restrict__ kw, const float* __restrict__ vw,
                           const float* __restrict__ pw) {
    int i = blockIdx.x * 256 + threadIdx.x;
    if (i >= PREP_TOT) return;
    const float* src; float* hi; float* lo; int off;
    if (i < XN)                      { src = x;  hi = g_xhi;  lo = g_xlo;  off = i; }
    else if (i < XN + QWN)           { src = qw; hi = g_qwhi; lo = g_qwlo; off = i - XN; }
    else if (i < XN + 2 * QWN)       { src = kw; hi = g_kwhi; lo = g_kwlo; off = i - XN - QWN; }
    else if (i < XN + 2 * QWN + VWN) { src = vw; hi = g_vwhi; lo = g_vwlo; off = i - XN - 2 * QWN; }
    else                             { src = pw; hi = g_pwhi; lo = g_pwlo; off = i - XN - 2 * QWN - VWN; }
    float v = src[off];
    uint32_t hb = f2tf32(v);
    hi[off] = __uint_as_float(hb);
    lo[off] = __uint_as_float(f2tf32(v - __uint_as_float(hb)));
}

// ======================================================================
// 3xTF32 GEMM mainloop: acc[8][4] += X[m0+128][K] @ W[n0+64][K]^T
// BM=128 BN=64 BK=32, 8 warps, double-buffered cp.async.
// ======================================================================
#define GB_XH 0
#define GB_XL 4608
#define GB_WH 9216
#define GB_WL 11520
#define GB_SZ 13824
#define GEMM_SMEM_FLOATS (2 * GB_SZ)          // 27648 floats = 110592 B

template<int KDIM>
__device__ __forceinline__ void gemm3x_main(
    const float* __restrict__ Xhi, const float* __restrict__ Xlo,
    const float* __restrict__ Whi, const float* __restrict__ Wlo,
    int m0, int n0, float* smp, uint32_t smb, float acc[8][4])
{
    const int t = threadIdx.x, w = t >> 5, lane = t & 31;
    const int gid = lane >> 2, tig = lane & 3;

    auto issue = [&](int k0, int b) {
        #pragma unroll
        for (int i = 0; i < 4; i++) {
            int idx = t + i * 256;
            int r = idx >> 3, f4 = idx & 7;
            cp_async16(smb + (b * GB_SZ + GB_XH + r * 36 + f4 * 4) * 4,
                       Xhi + (m0 + r) * KDIM + k0 + f4 * 4);
            cp_async16(smb + (b * GB_SZ + GB_XL + r * 36 + f4 * 4) * 4,
                       Xlo + (m0 + r) * KDIM + k0 + f4 * 4);
        }
        #pragma unroll
        for (int i = 0; i < 2; i++) {
            int idx = t + i * 256;
            int r = idx >> 3, f4 = idx & 7;
            cp_async16(smb + (b * GB_SZ + GB_WH + r * 36 + f4 * 4) * 4,
                       Whi + (n0 + r) * KDIM + k0 + f4 * 4);
            cp_async16(smb + (b * GB_SZ + GB_WL + r * 36 + f4 * 4) * 4,
                       Wlo + (n0 + r) * KDIM + k0 + f4 * 4);
        }
    };

    issue(0, 0);
    cp_commit();

    const int NT = KDIM / 32;
    for (int kt = 0; kt < NT; kt++) {
        const int b = kt & 1;
        if (kt + 1 < NT) {
            issue((kt + 1) * 32, b ^ 1);
            cp_commit();
            asm volatile("cp.async.wait_group 1;");
        } else {
            asm volatile("cp.async.wait_group 0;");
        }
        __syncthreads();

        float* XH = smp + b * GB_SZ + GB_XH;
        float* XL = smp + b * GB_SZ + GB_XL;
        float* WH = smp + b * GB_SZ + GB_WH;
        float* WL = smp + b * GB_SZ + GB_WL;

        #pragma unroll
        for (int ks = 0; ks < 4; ks++) {
            const int row = w * 16 + gid;
            const int kc = ks * 8 + tig;
            uint32_t ah0 = __float_as_uint(XH[row * 36 + kc]);
            uint32_t ah1 = __float_as_uint(XH[(row + 8) * 36 + kc]);
            uint32_t ah2 = __float_as_uint(XH[row * 36 + kc + 4]);
            uint32_t ah3 = __float_as_uint(XH[(row + 8) * 36 + kc + 4]);
            uint32_t al0 = __float_as_uint(XL[row * 36 + kc]);
            uint32_t al1 = __float_as_uint(XL[(row + 8) * 36 + kc]);
            uint32_t al2 = __float_as_uint(XL[row * 36 + kc + 4]);
            uint32_t al3 = __float_as_uint(XL[(row + 8) * 36 + kc + 4]);
            #pragma unroll
            for (int nt = 0; nt < 8; nt++) {
                const int nr = nt * 8 + gid;
                uint32_t bh0 = __float_as_uint(WH[nr * 36 + kc]);
                uint32_t bh1 = __float_as_uint(WH[nr * 36 + kc + 4]);
                uint32_t bl0 = __float_as_uint(WL[nr * 36 + kc]);
                uint32_t bl1 = __float_as_uint(WL[nr * 36 + kc + 4]);
                mma_tf32(acc[nt][0], acc[nt][1], acc[nt][2], acc[nt][3],
                         ah0, ah1, ah2, ah3, bh0, bh1);
                mma_tf32(acc[nt][0], acc[nt][1], acc[nt][2], acc[nt][3],
                         al0, al1, al2, al3, bh0, bh1);
                mma_tf32(acc[nt][0], acc[nt][1], acc[nt][2], acc[nt][3],
                         ah0, ah1, ah2, ah3, bl0, bl1);
            }
        }
        __syncthreads();
    }
}

// ======================================================================
// Fused QKV projection via 3xTF32 mma. grid (18, 24).
// y<4: Q, y<8: K, else V.  Epilogues write attn-ready layouts.
// ======================================================================
__global__ __launch_bounds__(256, 1)
void qkv_mma(const float* __restrict__ qbias, const float* __restrict__ kbias,
             const float* __restrict__ vbias) {
    extern __shared__ float smp[];
    const uint32_t smb = (uint32_t)__cvta_generic_to_shared(smp);
    const int t = threadIdx.x, w = t >> 5, lane = t & 31;
    const int gid = lane >> 2, tig = lane & 3;
    const int m0 = blockIdx.x * 128;
    const int y = blockIdx.y;

    int seg, nbase;
    const float *Whi, *Wlo, *B;
    if (y < 4)      { seg = 0; Whi = g_qwhi; Wlo = g_qwlo; B = qbias; nbase = y * 64; }
    else if (y < 8) { seg = 1; Whi = g_kwhi; Wlo = g_kwlo; B = kbias; nbase = (y - 4) * 64; }
    else            { seg = 2; Whi = g_vwhi; Wlo = g_vwlo; B = vbias; nbase = (y - 8) * 64; }

    float acc[8][4];
    #pragma unroll
    for (int nt = 0; nt < 8; nt++)
        #pragma unroll
        for (int i = 0; i < 4; i++) acc[nt][i] = 0.0f;

    gemm3x_main<DIM>(g_xhi, g_xlo, Whi, Wlo, m0, nbase, smp, smb, acc);

    const int mA = m0 + w * 16 + gid;
    const int mB = mA + 8;
    #pragma unroll
    for (int nt = 0; nt < 8; nt++) {
        const int n = nbase + nt * 8 + 2 * tig;
        const float bv0 = B[n], bv1 = B[n + 1];
        float v00 = acc[nt][0] + bv0, v01 = acc[nt][1] + bv1;
        float v10 = acc[nt][2] + bv0, v11 = acc[nt][3] + bv1;
        if (seg == 0) {
            int hh = n >> 5, c = n & 31;
            float* d0 = &g_qh[(hh * N_TOK + mA) * KD + c];
            float* d1 = &g_qh[(hh * N_TOK + mB) * KD + c];
            d0[0] = v00; d0[1] = v01;
            d1[0] = v10; d1[1] = v11;
        } else if (seg == 1) {
            int hh = n >> 5, c = n & 31;
            int iA = (hh * N_TOK + mA) * KD + c;
            int iB = (hh * N_TOK + mB) * KD + c;
            uint32_t h00 = f2tf32(v00), h01 = f2tf32(v01);
            uint32_t h10 = f2tf32(v10), h11 = f2tf32(v11);
            g_khi[iA] = __uint_as_float(h00); g_khi[iA + 1] = __uint_as_float(h01);
            g_khi[iB] = __uint_as_float(h10); g_khi[iB + 1] = __uint_as_float(h11);
            g_klo[iA]     = __uint_as_float(f2tf32(v00 - __uint_as_float(h00)));
            g_klo[iA + 1] = __uint_as_float(f2tf32(v01 - __uint_as_float(h01)));
            g_klo[iB]     = __uint_as_float(f2tf32(v10 - __uint_as_float(h10)));
            g_klo[iB + 1] = __uint_as_float(f2tf32(v11 - __uint_as_float(h11)));
        } else {
            int hh = n >> 7, c = n & 127;
            int iA = (hh * N_TOK + mA) * DV + c;
            int iB = (hh * N_TOK + mB) * DV + c;
            g_vt[iA]     = __uint_as_float(f2tf32(v00));
            g_vt[iA + 1] = __uint_as_float(f2tf32(v01));
            g_vt[iB]     = __uint_as_float(f2tf32(v10));
            g_vt[iB + 1] = __uint_as_float(f2tf32(v11));
        }
    }
}

// ======================================================================
// Output projection via 3xTF32 mma. grid (18, 6). K = 1024 (g_ohi/g_olo).
// ======================================================================
__global__ __launch_bounds__(256, 1)
void proj_mma(const float* __restrict__ pbias, float* __restrict__ out) {
    extern __shared__ float smp[];
    const uint32_t smb = (uint32_t)__cvta_generic_to_shared(smp);
    const int t = threadIdx.x, w = t >> 5, lane = t & 31;
    const int gid = lane >> 2, tig = lane & 3;
    const int m0 = blockIdx.x * 128;
    const int n0 = blockIdx.y * 64;

    float acc[8][4];
    #pragma unroll
    for (int nt = 0; nt < 8; nt++)
        #pragma unroll
        for (int i = 0; i < 4; i++) acc[nt][i] = 0.0f;

    gemm3x_main<DH>(g_ohi, g_olo, g_pwhi, g_pwlo, m0, n0, smp, smb, acc);

    const int mA = m0 + w * 16 + gid;
    const int mB = mA + 8;
    #pragma unroll
    for (int nt = 0; nt < 8; nt++) {
        const int n = n0 + nt * 8 + 2 * tig;
        const float bv0 = pbias[n], bv1 = pbias[n + 1];
        float2 r0, r1;
        r0.x = acc[nt][0] + bv0; r0.y = acc[nt][1] + bv1;
        r1.x = acc[nt][2] + bv0; r1.y = acc[nt][3] + bv1;
        *(float2*)&out[mA * DIM + n] = r0;
        *(float2*)&out[mB * DIM + n] = r1;
    }
}

// ======================================================================
// Flash attention, tf32 mma, cp.async double-buffered pipeline.
// Grid (18, 8), 256 threads (8 warps), BM=128 q rows, key tiles of 64.
// ======================================================================
#define BM 128
#define BN 64
#define NTILE (N_TOK / BN)
#define KSTR 36
#define VSTR 136
#define PSTR 68

#define OF_K(b)  ((b) * 4608)            // Khi at +0, Klo at +2304
#define OF_V(b)  (9216 + (b) * 8704)
#define OF_PS    26624
#define OF_BIA   35328
#define SM_TOT   37632                    // floats = 150528 bytes

__global__ __launch_bounds__(256, 1)
void attn_mma(const float* __restrict__ Qg,
              const float* __restrict__ Khig,
              const float* __restrict__ Klog,
              const float* __restrict__ Vg,
              const float* __restrict__ biases) {   // [8, 2304]
    extern __shared__ float sm[];
    const uint32_t smb = (uint32_t)__cvta_generic_to_shared(sm);
    float* Ps = sm + OF_PS;
    float* bias_sm = sm + OF_BIA;

    const int t    = threadIdx.x;
    const int w    = t >> 5;
    const int lane = t & 31;
    const int gid  = lane >> 2;
    const int tig  = lane & 3;
    const int qb   = blockIdx.x * BM;
    const int h    = blockIdx.y;

    const float* Kh_base = Khig + (h * N_TOK) * KD;
    const float* Kl_base = Klog + (h * N_TOK) * KD;
    const float* V_base  = Vg   + (h * N_TOK) * DV;

    const int row0 = qb + 16 * w + gid;
    const int row1 = row0 + 8;
    const int qy0 = row0 / RES, qx0 = row0 % RES;
    const int qy1 = row1 / RES, qx1 = row1 % RES;

    for (int i = t; i < N_TOK; i += 256)
        bias_sm[i] = biases[h * N_TOK + i];

    // loop-invariant Q fragments
    uint32_t qhi[4][4], qlo[4][4];
    {
        const float* Qrow0 = Qg + (h * N_TOK + row0) * KD;
        const float* Qrow1 = Qg + (h * N_TOK + row1) * KD;
        #pragma unroll
        for (int ks = 0; ks < 4; ks++) {
            float x0 = Qrow0[ks * 8 + tig];
            float x1 = Qrow1[ks * 8 + tig];
            float x2 = Qrow0[ks * 8 + tig + 4];
            float x3 = Qrow1[ks * 8 + tig + 4];
            uint32_t h0 = f2tf32(x0), h1 = f2tf32(x1), h2 = f2tf32(x2), h3 = f2tf32(x3);
            qhi[ks][0] = h0; qhi[ks][1] = h1; qhi[ks][2] = h2; qhi[ks][3] = h3;
            qlo[ks][0] = f2tf32(x0 - __uint_as_float(h0));
            qlo[ks][1] = f2tf32(x1 - __uint_as_float(h1));
            qlo[ks][2] = f2tf32(x2 - __uint_as_float(h2));
            qlo[ks][3] = f2tf32(x3 - __uint_as_float(h3));
        }
    }

    auto issue_tile = [&](int kt, int b) {
        const int kb = kt * BN;
        const float* kh = Kh_base + kb * KD;
        const float* kl = Kl_base + kb * KD;
        const float* vv = V_base + kb * DV;
        #pragma unroll
        for (int i = 0; i < 2; i++) {
            int c = t + i * 256;
            int r = c >> 3, f4 = c & 7;
            cp_async16(smb + (OF_K(b) + r * KSTR + f4 * 4) * 4, kh + r * KD + f4 * 4);
            cp_async16(smb + (OF_K(b) + 2304 + r * KSTR + f4 * 4) * 4, kl + r * KD + f4 * 4);
        }
        #pragma unroll
        for (int i = 0; i < 8; i++) {
            int c = t + i * 256;
            int r = c >> 5, f4 = c & 31;
            cp_async16(smb + (OF_V(b) + r * VSTR + f4 * 4) * 4, vv + r * DV + f4 * 4);
        }
    };

    float m_r0 = -1e30f, m_r1 = -1e30f;
    float l_r0 = 0.0f,   l_r1 = 0.0f;
    float o[16][4];
    #pragma unroll
    for (int nt = 0; nt < 16; nt++)
        #pragma unroll
        for (int i = 0; i < 4; i++) o[nt][i] = 0.0f;

    issue_tile(0, 0);
    cp_commit();

    for (int kt = 0; kt < NTILE; kt++) {
        const int b  = kt & 1;
        const int kb = kt * BN;
        float* Khi = sm + OF_K(b);
        float* Klo = Khi + 2304;
        float* Vs  = sm + OF_V(b);

        if (kt + 1 < NTILE) {
            issue_tile(kt + 1, b ^ 1);
            cp_commit();
            asm volatile("cp.async.wait_group 1;");
        } else {
            asm volatile("cp.async.wait_group 0;");
        }
        __syncthreads();

        // ---- S = Q K^T (3x tf32) ----
        float sfr[8][4];
        #pragma unroll
        for (int nt = 0; nt < 8; nt++)
            #pragma unroll
            for (int i = 0; i < 4; i++) sfr[nt][i] = 0.0f;

        #pragma unroll
        for (int ks = 0; ks < 4; ks++) {
            #pragma unroll
            for (int nt = 0; nt < 8; nt++) {
                int nrow = nt * 8 + gid;
                uint32_t bh0 = __float_as_uint(Khi[nrow * KSTR + ks * 8 + tig]);
                uint32_t bh1 = __float_as_uint(Khi[nrow * KSTR + ks * 8 + tig + 4]);
                uint32_t bl0 = __float_as_uint(Klo[nrow * KSTR + ks * 8 + tig]);
                uint32_t bl1 = __float_as_uint(Klo[nrow * KSTR + ks * 8 + tig + 4]);
                mma_tf32(sfr[nt][0], sfr[nt][1], sfr[nt][2], sfr[nt][3],
                         qhi[ks][0], qhi[ks][1], qhi[ks][2], qhi[ks][3], bh0, bh1);
                mma_tf32(sfr[nt][0], sfr[nt][1], sfr[nt][2], sfr[nt][3],
                         qlo[ks][0], qlo[ks][1], qlo[ks][2], qlo[ks][3], bh0, bh1);
                mma_tf32(sfr[nt][0], sfr[nt][1], sfr[nt][2], sfr[nt][3],
                         qhi[ks][0], qhi[ks][1], qhi[ks][2], qhi[ks][3], bl0, bl1);
            }
        }

        // ---- scale + bias, row max ----
        float mx0 = -1e30f, mx1 = -1e30f;
        #pragma unroll
        for (int nt = 0; nt < 8; nt++) {
            int ck0 = kb + nt * 8 + 2 * tig;
            int ck1 = ck0 + 1;
            int ky0 = ck0 / RES, kx0 = ck0 % RES;
            int ky1 = ck1 / RES, kx1 = ck1 % RES;
            float b00 = bias_sm[abs(qy0 - ky0) * RES + abs(qx0 - kx0)];
            float b01 = bias_sm[abs(qy0 - ky1) * RES + abs(qx0 - kx1)];
            float b10 = bias_sm[abs(qy1 - ky0) * RES + abs(qx1 - kx0)];
            float b11 = bias_sm[abs(qy1 - ky1) * RES + abs(qx1 - kx1)];
            sfr[nt][0] = sfr[nt][0] * QSCALE + b00;
            sfr[nt][1] = sfr[nt][1] * QSCALE + b01;
            sfr[nt][2] = sfr[nt][2] * QSCALE + b10;
            sfr[nt][3] = sfr[nt][3] * QSCALE + b11;
            mx0 = fmaxf(mx0, fmaxf(sfr[nt][0], sfr[nt][1]));
            mx1 = fmaxf(mx1, fmaxf(sfr[nt][2], sfr[nt][3]));
        }
        mx0 = fmaxf(mx0, __shfl_xor_sync(0xffffffffu, mx0, 1));
        mx0 = fmaxf(mx0, __shfl_xor_sync(0xffffffffu, mx0, 2));
        mx1 = fmaxf(mx1, __shfl_xor_sync(0xffffffffu, mx1, 1));
        mx1 = fmaxf(mx1, __shfl_xor_sync(0xffffffffu, mx1, 2));

        float mn0 = fmaxf(m_r0, mx0);
        float mn1 = fmaxf(m_r1, mx1);
        float al0 = __expf(m_r0 - mn0);
        float al1 = __expf(m_r1 - mn1);
        m_r0 = mn0; m_r1 = mn1;

        // ---- P = exp(S - m), tf32 into smem, row sums ----
        float sum0 = 0.0f, sum1 = 0.0f;
        const int prow0 = (16 * w + gid) * PSTR;
        const int prow1 = (16 * w + gid + 8) * PSTR;
        #pragma unroll
        for (int nt = 0; nt < 8; nt++) {
            float p0 = __expf(sfr[nt][0] - mn0);
            float p1 = __expf(sfr[nt][1] - mn0);
            float p2 = __expf(sfr[nt][2] - mn1);
            float p3 = __expf(sfr[nt][3] - mn1);
            sum0 += p0 + p1;
            sum1 += p2 + p3;
            float2 w0, w1;
            w0.x = __uint_as_float(f2tf32(p0));
            w0.y = __uint_as_float(f2tf32(p1));
            w1.x = __uint_as_float(f2tf32(p2));
            w1.y = __uint_as_float(f2tf32(p3));
            *(float2*)&Ps[prow0 + nt * 8 + 2 * tig] = w0;
            *(float2*)&Ps[prow1 + nt * 8 + 2 * tig] = w1;
        }
        sum0 += __shfl_xor_sync(0xffffffffu, sum0, 1);
        sum0 += __shfl_xor_sync(0xffffffffu, sum0, 2);
        sum1 += __shfl_xor_sync(0xffffffffu, sum1, 1);
        sum1 += __shfl_xor_sync(0xffffffffu, sum1, 2);
        l_r0 = l_r0 * al0 + sum0;
        l_r1 = l_r1 * al1 + sum1;

        #pragma unroll
        for (int nt = 0; nt < 16; nt++) {
            o[nt][0] *= al0; o[nt][1] *= al0;
            o[nt][2] *= al1; o[nt][3] *= al1;
        }
        __syncthreads();

        // ---- O += P * V (1x tf32) ----
        #pragma unroll
        for (int ks = 0; ks < 8; ks++) {
            uint32_t pa0 = __float_as_uint(Ps[prow0 + ks * 8 + tig]);
            uint32_t pa1 = __float_as_uint(Ps[prow1 + ks * 8 + tig]);
            uint32_t pa2 = __float_as_uint(Ps[prow0 + ks * 8 + tig + 4]);
            uint32_t pa3 = __float_as_uint(Ps[prow1 + ks * 8 + tig + 4]);
            #pragma unroll
            for (int nt = 0; nt < 16; nt++) {
                uint32_t vb0 = __float_as_uint(Vs[(ks * 8 + tig) * VSTR + nt * 8 + gid]);
                uint32_t vb1 = __float_as_uint(Vs[(ks * 8 + tig + 4) * VSTR + nt * 8 + gid]);
                mma_tf32(o[nt][0], o[nt][1], o[nt][2], o[nt][3],
                         pa0, pa1, pa2, pa3, vb0, vb1);
            }
        }
        __syncthreads();
    }

    // ---- epilogue: normalize, split hi/lo for proj ----
    float inv0 = 1.0f / l_r0;
    float inv1 = 1.0f / l_r1;
    #pragma unroll
    for (int nt = 0; nt < 16; nt++) {
        float v00 = o[nt][0] * inv0, v01 = o[nt][1] * inv0;
        float v10 = o[nt][2] * inv1, v11 = o[nt][3] * inv1;
        uint32_t h00 = f2tf32(v00), h01 = f2tf32(v01);
        uint32_t h10 = f2tf32(v10), h11 = f2tf32(v11);
        float2 hi0, hi1, lo0, lo1;
        hi0.x = __uint_as_float(h00); hi0.y = __uint_as_float(h01);
        hi1.x = __uint_as_float(h10); hi1.y = __uint_as_float(h11);
        lo0.x = __uint_as_float(f2tf32(v00 - __uint_as_float(h00)));
        lo0.y = __uint_as_float(f2tf32(v01 - __uint_as_float(h01)));
        lo1.x = __uint_as_float(f2tf32(v10 - __uint_as_float(h10)));
        lo1.y = __uint_as_float(f2tf32(v11 - __uint_as_float(h11)));
        long iA = (long)row0 * DH + h * DV + nt * 8 + 2 * tig;
        long iB = (long)row1 * DH + h * DV + nt * 8 + 2 * tig;
        *(float2*)&g_ohi[iA] = hi0;
        *(float2*)&g_ohi[iB] = hi1;
        *(float2*)&g_olo[iA] = lo0;
        *(float2*)&g_olo[iB] = lo1;
    }
}

// ======================================================================
extern "C" void kernel_launch(void* const* d_in, const int* in_sizes, int n_in,
                              void* d_out, int out_size) {
    const float* x       = (const float*)d_in[0];
    const float* q_w     = (const float*)d_in[1];
    const float* q_b     = (const float*)d_in[2];
    const float* k_w     = (const float*)d_in[3];
    const float* k_b     = (const float*)d_in[4];
    const float* v_w     = (const float*)d_in[5];
    const float* v_b     = (const float*)d_in[6];
    const float* proj_w  = (const float*)d_in[7];
    const float* proj_b  = (const float*)d_in[8];
    const float* abias   = (const float*)d_in[9];
    float* out           = (float*)d_out;

    float *pq, *pkh, *pkl, *pv;
    cudaGetSymbolAddress((void**)&pq,  g_qh);
    cudaGetSymbolAddress((void**)&pkh, g_khi);
    cudaGetSymbolAddress((void**)&pkl, g_klo);
    cudaGetSymbolAddress((void**)&pv,  g_vt);

    // 1. hi/lo split of x + weights
    split_prep<<<PREP_TOT / 256, 256>>>(x, q_w, k_w, v_w, proj_w);

    // 2. fused QKV projection (3xTF32 mma)
    const int gemm_smem = GEMM_SMEM_FLOATS * (int)sizeof(float);
    cudaFuncSetAttribute(qkv_mma, cudaFuncAttributeMaxDynamicSharedMemorySize, gemm_smem);
    qkv_mma<<<dim3(N_TOK / 128, 24), 256, gemm_smem>>>(q_b, k_b, v_b);

    // 3. fused attention (tf32 mma flash, cp.async pipelined)
    const int attn_smem = SM_TOT * (int)sizeof(float);
    cudaFuncSetAttribute(attn_mma, cudaFuncAttributeMaxDynamicSharedMemorySize, attn_smem);
    attn_mma<<<dim3(N_TOK / BM, NHEAD), 256, attn_smem>>>(pq, pkh, pkl, pv, abias);

    // 4. output projection (3xTF32 mma) -> d_out
    cudaFuncSetAttribute(proj_mma, cudaFuncAttributeMaxDynamicSharedMemorySize, gemm_smem);
    proj_mma<<<dim3(N_TOK / 128, 6), 256, gemm_smem>>>(proj_b, out);
}